// round 5
// baseline (speedup 1.0000x reference)
#include <cuda_runtime.h>
#include <cuda_fp16.h>

// BilateralSliceApply on GB300 — Round 5.
// grid (4,16,16,8,12) f32, guide (4,1024,1024), inp/out (4,1024,1024,3).
//
// R4 analysis: L1 66% / DRAM 38% / issue 53% at occ 54% — latency-limited,
// regs=46 capped residency at 5 blocks/SM. R5: cap at 6 blocks/SM
// (launch_bounds(256,6)) and restructure for short live ranges:
// inputs loaded incrementally, outputs stored as soon as each float4
// completes (they straddle pixel pairs). Memory structure unchanged:
// per-row fp16 PY plane (y-interp hoisted), 4 conflict-free LDS.64 taps
// + HFMA2 accumulation, all pixel I/O as .128 transactions.

#define GH 16
#define GW 16
#define GD 8
#define HH 1024
#define WW 1024
#define TPB 256
#define NXS 18               // 16 x cells + halo each side (xbase = -1)

__device__ __forceinline__ __half2 u2h(unsigned v) {
    __half2 h; asm("mov.b32 %0, %1;" : "=r"(*(unsigned*)&h) : "r"(v)); return h;
}

__global__ void __launch_bounds__(TPB, 6) bsa_kernel(
    const float* __restrict__ grid,
    const float* __restrict__ guide,
    const float* __restrict__ inp,
    float* __restrict__ out)
{
    __shared__ uint2 PY[NXS * GD * 3];   // [xi][z][12 halves], 3.375 KB

    const int y   = blockIdx.x;
    const int b   = blockIdx.y;
    const int tid = threadIdx.x;
    const int x0  = tid * 4;

    const size_t rowpix = (size_t)(b * HH + y) * WW;
    const float4* ibase = reinterpret_cast<const float4*>(inp + rowpix * 3);
    float4* obase = reinterpret_cast<float4*>(out + rowpix * 3);

    // early loads: guide (needed at p=0) and first input vector
    const float4 g4 = __ldg(reinterpret_cast<const float4*>(guide + rowpix) + tid);
    float4 ia = __ldg(ibase + tid * 3 + 0);
    float4 ib = __ldg(ibase + tid * 3 + 1);

    // y taps (uniform over row): gy - 0.5 = (2y-63)/128
    const int vy = 2 * y - 63;
    const int fy = vy >> 7;
    const float wy1 = (float)(vy & 127) * (1.0f / 128.0f);
    const float wy0 = 1.0f - wy1;
    const int cy0 = min(max(fy,     0), GH - 1);
    const int cy1 = min(max(fy + 1, 0), GH - 1);

    // stage PY = fp16(wy0*grid[cy0] + wy1*grid[cy1]), 432 uint2 entries
    #pragma unroll
    for (int e = tid; e < NXS * GD * 3; e += TPB) {
        const int c4 = e % 3;
        const int z  = (e / 3) & (GD - 1);
        const int xi = e / (3 * GD);
        const int gx = min(max(xi - 1, 0), GW - 1);
        const float4* g0 = reinterpret_cast<const float4*>(grid)
            + (size_t)(((b * GH + cy0) * GW + gx) * GD + z) * 3 + c4;
        const float4* g1 = reinterpret_cast<const float4*>(grid)
            + (size_t)(((b * GH + cy1) * GW + gx) * GD + z) * 3 + c4;
        const float4 a  = __ldg(g0);
        const float4 bb = __ldg(g1);
        const __half2 h0 = __floats2half2_rn(wy0 * a.x + wy1 * bb.x,
                                             wy0 * a.y + wy1 * bb.y);
        const __half2 h1 = __floats2half2_rn(wy0 * a.z + wy1 * bb.z,
                                             wy0 * a.w + wy1 * bb.w);
        uint2 v;
        v.x = *(const unsigned*)&h0;
        v.y = *(const unsigned*)&h1;
        PY[e] = v;
    }
    __syncthreads();

    // x taps: cell uniform over the thread's 4 px (fx flips only at x=32+64k)
    const int vx = 2 * x0 - 63;
    const int fx = vx >> 7;
    const float wx1base = (float)(vx & 127) * (1.0f / 128.0f);
    const int ebase0 = (fx + 1) * (GD * 3);
    const int ebase1 = ebase0 + GD * 3;

    float4 ic;                 // loaded after p=0
    float o0 = 0.f, o1 = 0.f, o2 = 0.f;   // carry partial float4 across pixels

    #pragma unroll
    for (int p = 0; p < 4; p++) {
        const float gv = (p == 0) ? g4.x : (p == 1) ? g4.y : (p == 2) ? g4.z : g4.w;
        const float wx1 = wx1base + (float)p * (2.0f / 128.0f);
        const float wx0 = 1.0f - wx1;

        // z taps
        const float tz = fmaf(gv, (float)GD, -0.5f);
        const float fz = floorf(tz);
        const float wz1 = tz - fz;
        const float wz0 = 1.0f - wz1;
        const int iz = (int)fz;
        const int z0 = min(max(iz,     0), GD - 1);
        const int z1 = min(max(iz + 1, 0), GD - 1);

        const __half2 W00 = __float2half2_rn(wx0 * wz0);
        const __half2 W01 = __float2half2_rn(wx0 * wz1);
        const __half2 W10 = __float2half2_rn(wx1 * wz0);
        const __half2 W11 = __float2half2_rn(wx1 * wz1);

        const int e00 = ebase0 + z0 * 3;
        const int e01 = ebase0 + z1 * 3;
        const int e10 = ebase1 + z0 * 3;
        const int e11 = ebase1 + z1 * 3;

        __half2 a0 = __float2half2_rn(0.f), a1 = a0, a2 = a0,
                a3 = a0, a4 = a0, a5 = a0;
        {
            const uint2 q0 = PY[e00], q1 = PY[e00 + 1], q2 = PY[e00 + 2];
            a0 = __hfma2(u2h(q0.x), W00, a0); a1 = __hfma2(u2h(q0.y), W00, a1);
            a2 = __hfma2(u2h(q1.x), W00, a2); a3 = __hfma2(u2h(q1.y), W00, a3);
            a4 = __hfma2(u2h(q2.x), W00, a4); a5 = __hfma2(u2h(q2.y), W00, a5);
        }
        {
            const uint2 q0 = PY[e01], q1 = PY[e01 + 1], q2 = PY[e01 + 2];
            a0 = __hfma2(u2h(q0.x), W01, a0); a1 = __hfma2(u2h(q0.y), W01, a1);
            a2 = __hfma2(u2h(q1.x), W01, a2); a3 = __hfma2(u2h(q1.y), W01, a3);
            a4 = __hfma2(u2h(q2.x), W01, a4); a5 = __hfma2(u2h(q2.y), W01, a5);
        }
        {
            const uint2 q0 = PY[e10], q1 = PY[e10 + 1], q2 = PY[e10 + 2];
            a0 = __hfma2(u2h(q0.x), W10, a0); a1 = __hfma2(u2h(q0.y), W10, a1);
            a2 = __hfma2(u2h(q1.x), W10, a2); a3 = __hfma2(u2h(q1.y), W10, a3);
            a4 = __hfma2(u2h(q2.x), W10, a4); a5 = __hfma2(u2h(q2.y), W10, a5);
        }
        {
            const uint2 q0 = PY[e11], q1 = PY[e11 + 1], q2 = PY[e11 + 2];
            a0 = __hfma2(u2h(q0.x), W11, a0); a1 = __hfma2(u2h(q0.y), W11, a1);
            a2 = __hfma2(u2h(q1.x), W11, a2); a3 = __hfma2(u2h(q1.y), W11, a3);
            a4 = __hfma2(u2h(q2.x), W11, a4); a5 = __hfma2(u2h(q2.y), W11, a5);
        }

        const float c0 = __low2float(a0), c1 = __high2float(a0);
        const float c2 = __low2float(a1), c3 = __high2float(a1);
        const float c4 = __low2float(a2), c5 = __high2float(a2);
        const float c6 = __low2float(a3), c7 = __high2float(a3);
        const float c8 = __low2float(a4), c9 = __high2float(a4);
        const float cA = __low2float(a5), cB = __high2float(a5);

        // pixel p input channels from the rolling float4 registers
        float i0, i1, i2;
        if (p == 0)      { i0 = ia.x; i1 = ia.y; i2 = ia.z; }
        else if (p == 1) { i0 = ia.w; i1 = ib.x; i2 = ib.y; }
        else if (p == 2) { i0 = ib.z; i1 = ib.w; i2 = ic.x; }
        else             { i0 = ic.y; i1 = ic.z; i2 = ic.w; }

        const float r0 = c0 * i0 + c1 * i1 + c2 * i2 + c3;
        const float r1 = c4 * i0 + c5 * i1 + c6 * i2 + c7;
        const float r2 = c8 * i0 + c9 * i1 + cA * i2 + cB;

        // stores straddle pixel pairs: flush a float4 when it completes
        if (p == 0) {
            ic = __ldg(ibase + tid * 3 + 2);     // needed from p=2
            o0 = r0; o1 = r1; o2 = r2;
        } else if (p == 1) {
            obase[tid * 3 + 0] = make_float4(o0, o1, o2, r0);
            o0 = r1; o1 = r2;
        } else if (p == 2) {
            obase[tid * 3 + 1] = make_float4(o0, o1, r0, r1);
            o0 = r2;
        } else {
            obase[tid * 3 + 2] = make_float4(o0, r0, r1, r2);
        }
    }
}

extern "C" void kernel_launch(void* const* d_in, const int* in_sizes, int n_in,
                              void* d_out, int out_size)
{
    const float* grid  = (const float*)d_in[0];
    const float* guide = (const float*)d_in[1];
    const float* inp   = (const float*)d_in[2];
    float* out = (float*)d_out;

    const int B = in_sizes[1] / (HH * WW);  // 4

    dim3 blk(TPB, 1, 1);
    dim3 grd(HH, B, 1);                     // one block per image row
    bsa_kernel<<<grd, blk>>>(grid, guide, inp, out);
}

// round 6
// speedup vs baseline: 1.0446x; 1.0446x over previous
#include <cuda_runtime.h>
#include <cuda_fp16.h>

// BilateralSliceApply on GB300 — Round 6.
// grid (4,16,16,8,12) f32, guide (4,1024,1024), inp/out (4,1024,1024,3).
//
// R5 lesson: latency-bound, not occupancy-bound. R6 = R4 structure
// (batched epilogue stores) + pixel-pair interleaving (2 independent
// tap-load + FMA streams per thread) + PY split into uint4/uint2 arrays
// (8 LDS issue slots per pixel instead of 12, same wavefront bytes).

#define GH 16
#define GW 16
#define GD 8
#define HH 1024
#define WW 1024
#define TPB 256
#define NXS 18               // 16 x cells + halo each side (xbase = -1)

__device__ __forceinline__ __half2 u2h(unsigned v) {
    __half2 h; asm("mov.b32 %0, %1;" : "=r"(*(unsigned*)&h) : "r"(v)); return h;
}

__global__ void __launch_bounds__(TPB) bsa_kernel(
    const float* __restrict__ grid,
    const float* __restrict__ guide,
    const float* __restrict__ inp,
    float* __restrict__ out)
{
    // channels 0..7 (4 half2) and 8..11 (2 half2), [xi][z] entries
    __shared__ uint4 PYa[NXS * GD];      // 2.25 KB
    __shared__ uint2 PYb[NXS * GD];      // 1.125 KB

    const int y   = blockIdx.x;
    const int b   = blockIdx.y;
    const int tid = threadIdx.x;
    const int x0  = tid * 4;

    const size_t rowpix = (size_t)(b * HH + y) * WW;
    const float4* ibase = reinterpret_cast<const float4*>(inp + rowpix * 3);
    float4* obase = reinterpret_cast<float4*>(out + rowpix * 3);

    // early global loads
    const float4 g4 = __ldg(reinterpret_cast<const float4*>(guide + rowpix) + tid);
    const float4 ia = __ldg(ibase + tid * 3 + 0);
    const float4 ib = __ldg(ibase + tid * 3 + 1);
    const float4 ic = __ldg(ibase + tid * 3 + 2);

    // y taps (uniform over row): gy - 0.5 = (2y-63)/128
    const int vy = 2 * y - 63;
    const int fy = vy >> 7;
    const float wy1 = (float)(vy & 127) * (1.0f / 128.0f);
    const float wy0 = 1.0f - wy1;
    const int cy0 = min(max(fy,     0), GH - 1);
    const int cy1 = min(max(fy + 1, 0), GH - 1);

    // stage: 144 (xi,z) entries, one thread each; 6 LDG.128 per entry
    if (tid < NXS * GD) {
        const int z  = tid & (GD - 1);
        const int xi = tid >> 3;
        const int gx = min(max(xi - 1, 0), GW - 1);
        const float4* g0 = reinterpret_cast<const float4*>(grid)
            + (size_t)(((b * GH + cy0) * GW + gx) * GD + z) * 3;
        const float4* g1 = reinterpret_cast<const float4*>(grid)
            + (size_t)(((b * GH + cy1) * GW + gx) * GD + z) * 3;
        const float4 p0 = __ldg(g0 + 0), p1 = __ldg(g0 + 1), p2 = __ldg(g0 + 2);
        const float4 q0 = __ldg(g1 + 0), q1 = __ldg(g1 + 1), q2 = __ldg(g1 + 2);
        const __half2 h01 = __floats2half2_rn(wy0*p0.x + wy1*q0.x, wy0*p0.y + wy1*q0.y);
        const __half2 h23 = __floats2half2_rn(wy0*p0.z + wy1*q0.z, wy0*p0.w + wy1*q0.w);
        const __half2 h45 = __floats2half2_rn(wy0*p1.x + wy1*q1.x, wy0*p1.y + wy1*q1.y);
        const __half2 h67 = __floats2half2_rn(wy0*p1.z + wy1*q1.z, wy0*p1.w + wy1*q1.w);
        const __half2 h89 = __floats2half2_rn(wy0*p2.x + wy1*q2.x, wy0*p2.y + wy1*q2.y);
        const __half2 hAB = __floats2half2_rn(wy0*p2.z + wy1*q2.z, wy0*p2.w + wy1*q2.w);
        uint4 va;
        va.x = *(const unsigned*)&h01; va.y = *(const unsigned*)&h23;
        va.z = *(const unsigned*)&h45; va.w = *(const unsigned*)&h67;
        uint2 vb;
        vb.x = *(const unsigned*)&h89; vb.y = *(const unsigned*)&hAB;
        PYa[tid] = va;
        PYb[tid] = vb;
    }
    __syncthreads();

    // x taps: cell uniform over the thread's 4 px
    const int vx = 2 * x0 - 63;
    const int fx = vx >> 7;
    const float wx1base = (float)(vx & 127) * (1.0f / 128.0f);
    const int eb0 = (fx + 1) * GD;       // x-cell base index (stride GD)
    const int eb1 = eb0 + GD;

    const float gin[4] = {g4.x, g4.y, g4.z, g4.w};
    float o[12];

    #pragma unroll
    for (int pp = 0; pp < 4; pp += 2) {
        // ---- z taps + weights for both pixels of the pair ----
        int i00[2], i01[2], i10[2], i11[2];
        __half2 W00[2], W01[2], W10[2], W11[2];
        #pragma unroll
        for (int q = 0; q < 2; q++) {
            const int p = pp + q;
            const float wx1 = wx1base + (float)p * (2.0f / 128.0f);
            const float wx0 = 1.0f - wx1;
            const float tz = fmaf(gin[p], (float)GD, -0.5f);
            const float fz = floorf(tz);
            const float wz1 = tz - fz;
            const float wz0 = 1.0f - wz1;
            const int iz = (int)fz;
            const int z0 = min(max(iz,     0), GD - 1);
            const int z1 = min(max(iz + 1, 0), GD - 1);
            i00[q] = eb0 + z0;  i01[q] = eb0 + z1;
            i10[q] = eb1 + z0;  i11[q] = eb1 + z1;
            W00[q] = __float2half2_rn(wx0 * wz0);
            W01[q] = __float2half2_rn(wx0 * wz1);
            W10[q] = __float2half2_rn(wx1 * wz0);
            W11[q] = __float2half2_rn(wx1 * wz1);
        }

        // ---- issue all 16 tap loads of the pair back-to-back ----
        uint4 A00[2], A01[2], A10[2], A11[2];
        uint2 B00[2], B01[2], B10[2], B11[2];
        #pragma unroll
        for (int q = 0; q < 2; q++) {
            A00[q] = PYa[i00[q]]; A01[q] = PYa[i01[q]];
            A10[q] = PYa[i10[q]]; A11[q] = PYa[i11[q]];
            B00[q] = PYb[i00[q]]; B01[q] = PYb[i01[q]];
            B10[q] = PYb[i10[q]]; B11[q] = PYb[i11[q]];
        }

        // ---- two independent FMA chains ----
        #pragma unroll
        for (int q = 0; q < 2; q++) {
            const int p = pp + q;
            __half2 a0 = __hmul2(u2h(A00[q].x), W00[q]);
            __half2 a1 = __hmul2(u2h(A00[q].y), W00[q]);
            __half2 a2 = __hmul2(u2h(A00[q].z), W00[q]);
            __half2 a3 = __hmul2(u2h(A00[q].w), W00[q]);
            __half2 a4 = __hmul2(u2h(B00[q].x), W00[q]);
            __half2 a5 = __hmul2(u2h(B00[q].y), W00[q]);

            a0 = __hfma2(u2h(A01[q].x), W01[q], a0);
            a1 = __hfma2(u2h(A01[q].y), W01[q], a1);
            a2 = __hfma2(u2h(A01[q].z), W01[q], a2);
            a3 = __hfma2(u2h(A01[q].w), W01[q], a3);
            a4 = __hfma2(u2h(B01[q].x), W01[q], a4);
            a5 = __hfma2(u2h(B01[q].y), W01[q], a5);

            a0 = __hfma2(u2h(A10[q].x), W10[q], a0);
            a1 = __hfma2(u2h(A10[q].y), W10[q], a1);
            a2 = __hfma2(u2h(A10[q].z), W10[q], a2);
            a3 = __hfma2(u2h(A10[q].w), W10[q], a3);
            a4 = __hfma2(u2h(B10[q].x), W10[q], a4);
            a5 = __hfma2(u2h(B10[q].y), W10[q], a5);

            a0 = __hfma2(u2h(A11[q].x), W11[q], a0);
            a1 = __hfma2(u2h(A11[q].y), W11[q], a1);
            a2 = __hfma2(u2h(A11[q].z), W11[q], a2);
            a3 = __hfma2(u2h(A11[q].w), W11[q], a3);
            a4 = __hfma2(u2h(B11[q].x), W11[q], a4);
            a5 = __hfma2(u2h(B11[q].y), W11[q], a5);

            const float c0 = __low2float(a0), c1 = __high2float(a0);
            const float c2 = __low2float(a1), c3 = __high2float(a1);
            const float c4 = __low2float(a2), c5 = __high2float(a2);
            const float c6 = __low2float(a3), c7 = __high2float(a3);
            const float c8 = __low2float(a4), c9 = __high2float(a4);
            const float cA = __low2float(a5), cB = __high2float(a5);

            float i0, i1, i2;
            if (p == 0)      { i0 = ia.x; i1 = ia.y; i2 = ia.z; }
            else if (p == 1) { i0 = ia.w; i1 = ib.x; i2 = ib.y; }
            else if (p == 2) { i0 = ib.z; i1 = ib.w; i2 = ic.x; }
            else             { i0 = ic.y; i1 = ic.z; i2 = ic.w; }

            o[3 * p + 0] = c0 * i0 + c1 * i1 + c2 * i2 + c3;
            o[3 * p + 1] = c4 * i0 + c5 * i1 + c6 * i2 + c7;
            o[3 * p + 2] = c8 * i0 + c9 * i1 + cA * i2 + cB;
        }
    }

    // batched epilogue stores (R4 style)
    obase[tid * 3 + 0] = make_float4(o[0], o[1], o[2],  o[3]);
    obase[tid * 3 + 1] = make_float4(o[4], o[5], o[6],  o[7]);
    obase[tid * 3 + 2] = make_float4(o[8], o[9], o[10], o[11]);
}

extern "C" void kernel_launch(void* const* d_in, const int* in_sizes, int n_in,
                              void* d_out, int out_size)
{
    const float* grid  = (const float*)d_in[0];
    const float* guide = (const float*)d_in[1];
    const float* inp   = (const float*)d_in[2];
    float* out = (float*)d_out;

    const int B = in_sizes[1] / (HH * WW);  // 4

    dim3 blk(TPB, 1, 1);
    dim3 grd(HH, B, 1);                     // one block per image row
    bsa_kernel<<<grd, blk>>>(grid, guide, inp, out);
}

// round 8
// speedup vs baseline: 1.0468x; 1.0022x over previous
#include <cuda_runtime.h>
#include <cuda_fp16.h>

// BilateralSliceApply on GB300 — Round 7.
// grid (4,16,16,8,12) f32, guide (4,1024,1024), inp/out (4,1024,1024,3).
//
// R6 analysis: ~26.5us kernel across 3 variants, no pipe saturated ->
// exposed per-block prologue (stage LDGs + barrier ~25% of block life).
// R7: one block = 4 consecutive rows. Stage 4 fp16 PY planes at once
// (rows share grid cells -> L1 hits), one barrier per 4 rows, guide/inp
// software-pipelined one row ahead. Inner loop = R6 pair-interleaved
// LDS.128+LDS.64 taps + HFMA2.

#define GH 16
#define GW 16
#define GD 8
#define HH 1024
#define WW 1024
#define TPB 256
#define NXS 18               // 16 x cells + halo each side (xbase = -1)
#define RPB 4                // rows per block
#define PLANE (NXS * GD)     // 144 entries per row plane

__device__ __forceinline__ __half2 u2h(unsigned v) {
    __half2 h; asm("mov.b32 %0, %1;" : "=r"(*(unsigned*)&h) : "r"(v)); return h;
}

__global__ void __launch_bounds__(TPB) bsa_kernel(
    const float* __restrict__ grid,
    const float* __restrict__ guide,
    const float* __restrict__ inp,
    float* __restrict__ out)
{
    // channels 0..7 (uint4) and 8..11 (uint2) per (row, xi, z)
    __shared__ uint4 PYa[RPB * PLANE];   // 9 KB
    __shared__ uint2 PYb[RPB * PLANE];   // 4.5 KB

    const int y0  = blockIdx.x * RPB;
    const int b   = blockIdx.y;
    const int tid = threadIdx.x;
    const int x0  = tid * 4;

    // ---- prefetch row 0 pixel data ----
    const size_t row0 = (size_t)(b * HH + y0) * WW;
    float4 g4n = __ldg(reinterpret_cast<const float4*>(guide + row0) + tid);
    const float4* ib0 = reinterpret_cast<const float4*>(inp + row0 * 3);
    float4 ian = __ldg(ib0 + tid * 3 + 0);
    float4 ibn = __ldg(ib0 + tid * 3 + 1);
    float4 icn = __ldg(ib0 + tid * 3 + 2);

    // ---- stage 4 PY planes: 576 entries over 256 threads ----
    #pragma unroll
    for (int e = tid; e < RPB * PLANE; e += TPB) {
        const int ent = e % PLANE;        // (xi,z) entry
        const int r   = e / PLANE;        // row in group
        const int z   = ent & (GD - 1);
        const int xi  = ent >> 3;
        const int gx  = min(max(xi - 1, 0), GW - 1);

        const int vy = 2 * (y0 + r) - 63;
        const int fy = vy >> 7;
        const float wy1 = (float)(vy & 127) * (1.0f / 128.0f);
        const float wy0 = 1.0f - wy1;
        const int cy0 = min(max(fy,     0), GH - 1);
        const int cy1 = min(max(fy + 1, 0), GH - 1);

        const float4* g0 = reinterpret_cast<const float4*>(grid)
            + (size_t)(((b * GH + cy0) * GW + gx) * GD + z) * 3;
        const float4* g1 = reinterpret_cast<const float4*>(grid)
            + (size_t)(((b * GH + cy1) * GW + gx) * GD + z) * 3;
        const float4 p0 = __ldg(g0 + 0), p1 = __ldg(g0 + 1), p2 = __ldg(g0 + 2);
        const float4 q0 = __ldg(g1 + 0), q1 = __ldg(g1 + 1), q2 = __ldg(g1 + 2);
        const __half2 h01 = __floats2half2_rn(wy0*p0.x + wy1*q0.x, wy0*p0.y + wy1*q0.y);
        const __half2 h23 = __floats2half2_rn(wy0*p0.z + wy1*q0.z, wy0*p0.w + wy1*q0.w);
        const __half2 h45 = __floats2half2_rn(wy0*p1.x + wy1*q1.x, wy0*p1.y + wy1*q1.y);
        const __half2 h67 = __floats2half2_rn(wy0*p1.z + wy1*q1.z, wy0*p1.w + wy1*q1.w);
        const __half2 h89 = __floats2half2_rn(wy0*p2.x + wy1*q2.x, wy0*p2.y + wy1*q2.y);
        const __half2 hAB = __floats2half2_rn(wy0*p2.z + wy1*q2.z, wy0*p2.w + wy1*q2.w);
        uint4 va;
        va.x = *(const unsigned*)&h01; va.y = *(const unsigned*)&h23;
        va.z = *(const unsigned*)&h45; va.w = *(const unsigned*)&h67;
        uint2 vb;
        vb.x = *(const unsigned*)&h89; vb.y = *(const unsigned*)&hAB;
        PYa[e] = va;
        PYb[e] = vb;
    }
    __syncthreads();

    // ---- x taps: row-invariant, hoisted ----
    const int vx = 2 * x0 - 63;
    const int fx = vx >> 7;
    const float wx1base = (float)(vx & 127) * (1.0f / 128.0f);
    const int eb0r = (fx + 1) * GD;      // x-cell base within a plane
    const int eb1r = eb0r + GD;

    #pragma unroll
    for (int r = 0; r < RPB; r++) {
        // consume prefetched row data
        const float4 g4 = g4n;
        const float4 ia = ian;
        const float4 ib = ibn;
        const float4 ic = icn;

        // prefetch next row
        if (r + 1 < RPB) {
            const size_t rn = (size_t)(b * HH + y0 + r + 1) * WW;
            g4n = __ldg(reinterpret_cast<const float4*>(guide + rn) + tid);
            const float4* ibn_p = reinterpret_cast<const float4*>(inp + rn * 3);
            ian = __ldg(ibn_p + tid * 3 + 0);
            ibn = __ldg(ibn_p + tid * 3 + 1);
            icn = __ldg(ibn_p + tid * 3 + 2);
        }

        const int eb0 = r * PLANE + eb0r;
        const int eb1 = r * PLANE + eb1r;
        const float gin[4] = {g4.x, g4.y, g4.z, g4.w};
        float o[12];

        #pragma unroll
        for (int pp = 0; pp < 4; pp += 2) {
            int i00[2], i01[2], i10[2], i11[2];
            __half2 W00[2], W01[2], W10[2], W11[2];
            #pragma unroll
            for (int q = 0; q < 2; q++) {
                const int p = pp + q;
                const float wx1 = wx1base + (float)p * (2.0f / 128.0f);
                const float wx0 = 1.0f - wx1;
                const float tz = fmaf(gin[p], (float)GD, -0.5f);
                const float fz = floorf(tz);
                const float wz1 = tz - fz;
                const float wz0 = 1.0f - wz1;
                const int iz = (int)fz;
                const int z0 = min(max(iz,     0), GD - 1);
                const int z1 = min(max(iz + 1, 0), GD - 1);
                i00[q] = eb0 + z0;  i01[q] = eb0 + z1;
                i10[q] = eb1 + z0;  i11[q] = eb1 + z1;
                W00[q] = __float2half2_rn(wx0 * wz0);
                W01[q] = __float2half2_rn(wx0 * wz1);
                W10[q] = __float2half2_rn(wx1 * wz0);
                W11[q] = __float2half2_rn(wx1 * wz1);
            }

            uint4 A00[2], A01[2], A10[2], A11[2];
            uint2 B00[2], B01[2], B10[2], B11[2];
            #pragma unroll
            for (int q = 0; q < 2; q++) {
                A00[q] = PYa[i00[q]]; A01[q] = PYa[i01[q]];
                A10[q] = PYa[i10[q]]; A11[q] = PYa[i11[q]];
                B00[q] = PYb[i00[q]]; B01[q] = PYb[i01[q]];
                B10[q] = PYb[i10[q]]; B11[q] = PYb[i11[q]];
            }

            #pragma unroll
            for (int q = 0; q < 2; q++) {
                const int p = pp + q;
                __half2 a0 = __hmul2(u2h(A00[q].x), W00[q]);
                __half2 a1 = __hmul2(u2h(A00[q].y), W00[q]);
                __half2 a2 = __hmul2(u2h(A00[q].z), W00[q]);
                __half2 a3 = __hmul2(u2h(A00[q].w), W00[q]);
                __half2 a4 = __hmul2(u2h(B00[q].x), W00[q]);
                __half2 a5 = __hmul2(u2h(B00[q].y), W00[q]);

                a0 = __hfma2(u2h(A01[q].x), W01[q], a0);
                a1 = __hfma2(u2h(A01[q].y), W01[q], a1);
                a2 = __hfma2(u2h(A01[q].z), W01[q], a2);
                a3 = __hfma2(u2h(A01[q].w), W01[q], a3);
                a4 = __hfma2(u2h(B01[q].x), W01[q], a4);
                a5 = __hfma2(u2h(B01[q].y), W01[q], a5);

                a0 = __hfma2(u2h(A10[q].x), W10[q], a0);
                a1 = __hfma2(u2h(A10[q].y), W10[q], a1);
                a2 = __hfma2(u2h(A10[q].z), W10[q], a2);
                a3 = __hfma2(u2h(A10[q].w), W10[q], a3);
                a4 = __hfma2(u2h(B10[q].x), W10[q], a4);
                a5 = __hfma2(u2h(B10[q].y), W10[q], a5);

                a0 = __hfma2(u2h(A11[q].x), W11[q], a0);
                a1 = __hfma2(u2h(A11[q].y), W11[q], a1);
                a2 = __hfma2(u2h(A11[q].z), W11[q], a2);
                a3 = __hfma2(u2h(A11[q].w), W11[q], a3);
                a4 = __hfma2(u2h(B11[q].x), W11[q], a4);
                a5 = __hfma2(u2h(B11[q].y), W11[q], a5);

                const float c0 = __low2float(a0), c1 = __high2float(a0);
                const float c2 = __low2float(a1), c3 = __high2float(a1);
                const float c4 = __low2float(a2), c5 = __high2float(a2);
                const float c6 = __low2float(a3), c7 = __high2float(a3);
                const float c8 = __low2float(a4), c9 = __high2float(a4);
                const float cA = __low2float(a5), cB = __high2float(a5);

                float i0, i1, i2;
                if (p == 0)      { i0 = ia.x; i1 = ia.y; i2 = ia.z; }
                else if (p == 1) { i0 = ia.w; i1 = ib.x; i2 = ib.y; }
                else if (p == 2) { i0 = ib.z; i1 = ib.w; i2 = ic.x; }
                else             { i0 = ic.y; i1 = ic.z; i2 = ic.w; }

                o[3 * p + 0] = c0 * i0 + c1 * i1 + c2 * i2 + c3;
                o[3 * p + 1] = c4 * i0 + c5 * i1 + c6 * i2 + c7;
                o[3 * p + 2] = c8 * i0 + c9 * i1 + cA * i2 + cB;
            }
        }

        // batched stores for this row
        float4* obase = reinterpret_cast<float4*>(
            out + (size_t)(b * HH + y0 + r) * WW * 3);
        obase[tid * 3 + 0] = make_float4(o[0], o[1], o[2],  o[3]);
        obase[tid * 3 + 1] = make_float4(o[4], o[5], o[6],  o[7]);
        obase[tid * 3 + 2] = make_float4(o[8], o[9], o[10], o[11]);
    }
}

extern "C" void kernel_launch(void* const* d_in, const int* in_sizes, int n_in,
                              void* d_out, int out_size)
{
    const float* grid  = (const float*)d_in[0];
    const float* guide = (const float*)d_in[1];
    const float* inp   = (const float*)d_in[2];
    float* out = (float*)d_out;

    const int B = in_sizes[1] / (HH * WW);  // 4

    dim3 blk(TPB, 1, 1);
    dim3 grd(HH / RPB, B, 1);               // (256, 4)
    bsa_kernel<<<grd, blk>>>(grid, guide, inp, out);
}